// round 13
// baseline (speedup 1.0000x reference)
#include <cuda_runtime.h>
#include <cuda_fp16.h>
#include <cstdint>

// ---------------- problem constants ----------------
#define D_DIM   1024
#define C_NUM   8192
#define N_TOT   16384
#define NBLK    128                      // row blocks of 128
#define NCOLB   64                       // col blocks of 256
#define NTILES  4160                     // tiles (I,J) with I <= 2J+1
#define PGRID   4144                     // 14 full waves at occ 2 x 148 SMs; 16 blocks run 2 tiles
#define NSLOT   190                      // 64 row-side + 126 col-side slots
#define KSTAGES 16                       // K = 1024 = 16 x 64 halves (128 B/row/stage)
#define A_BYTES (128 * 128)              // 16 KB (A: 128 rows x 64 f16)
#define B_BYTES (256 * 128)              // 32 KB (B: 256 rows x 64 f16)
#define STG_BYTES (A_BYTES + B_BYTES)    // 48 KB
#define SMEM_TOTAL (2 * STG_BYTES)       // 96 KB -> 2 CTAs/SM

#define H_SCALE 1.6986436005760381f      // sqrt(log2(e)/T), T=0.5 -> log2 domain
#define LN2_D   0.6931471805599453

// ---------------- device scratch (no allocs allowed) ----------------
__device__ __half g_Hh[(size_t)N_TOT * D_DIM];              // [n][d] K-major, 32 MB
__device__ float  g_pm[(size_t)NSLOT * N_TOT];              // [slot][row] max
__device__ float  g_ps[(size_t)NSLOT * N_TOT];              // [slot][row] sum
__device__ float  g_pos[N_TOT];
__device__ double g_partial[NBLK];

// ---------------- PTX helpers ----------------
static __device__ __forceinline__ uint32_t smem_u32(const void* p) {
    uint32_t a;
    asm("{ .reg .u64 t; cvta.to.shared.u64 t, %1; cvt.u32.u64 %0, t; }" : "=r"(a) : "l"(p));
    return a;
}
static __device__ __forceinline__ float ex2f(float x) {
    float y; asm("ex2.approx.ftz.f32 %0, %1;" : "=f"(y) : "f"(x)); return y;
}
static __device__ __forceinline__ float lg2f(float x) {
    float y; asm("lg2.approx.f32 %0, %1;" : "=f"(y) : "f"(x)); return y;
}
static __device__ __forceinline__ void cp16(uint32_t dst, uint64_t src) {
    asm volatile("cp.async.cg.shared.global [%0], [%1], 16;" :: "r"(dst), "l"(src) : "memory");
}
static __device__ __forceinline__ void ldsm4(uint32_t a, uint32_t& r0, uint32_t& r1,
                                             uint32_t& r2, uint32_t& r3) {
    asm volatile("ldmatrix.sync.aligned.m8n8.x4.shared.b16 {%0,%1,%2,%3}, [%4];"
                 : "=r"(r0), "=r"(r1), "=r"(r2), "=r"(r3) : "r"(a));
}
// f16 inputs, f16 accumulate
static __device__ __forceinline__ void mma16816h(uint32_t* d, const uint32_t* a,
                                                 uint32_t b0, uint32_t b1) {
    asm volatile(
        "mma.sync.aligned.m16n8k16.row.col.f16.f16.f16.f16 "
        "{%0,%1}, {%2,%3,%4,%5}, {%6,%7}, {%0,%1};"
        : "+r"(d[0]), "+r"(d[1])
        : "r"(a[0]), "r"(a[1]), "r"(a[2]), "r"(a[3]), "r"(b0), "r"(b1));
}

// ---------------- kernel 0: transpose + scale + f16 convert ----------------
__global__ void convert_kernel(const float* __restrict__ hi, const float* __restrict__ hj) {
    __shared__ float tile[32][33];
    const int tn = blockIdx.x, td = blockIdx.y;
    const int tx = threadIdx.x, ty = threadIdx.y;   // 32 x 8
    const int n0 = tn * 32, d0 = td * 32;
    const float* src = (n0 < C_NUM) ? hi : hj;
    const int nc = (n0 < C_NUM) ? n0 : (n0 - C_NUM);
#pragma unroll
    for (int k = 0; k < 32; k += 8)
        tile[ty + k][tx] = src[(size_t)(d0 + ty + k) * C_NUM + nc + tx];
    __syncthreads();
#pragma unroll
    for (int k = 0; k < 32; k += 8) {
        float v = tile[tx][ty + k];
        g_Hh[(size_t)(n0 + ty + k) * D_DIM + d0 + tx] = __float2half(v * H_SCALE);
    }
}

// ---------------- stage loader: A (128 rows of I) + B (256 rows of J) ----------------
static __device__ __forceinline__ void load_stage(uint32_t sbase, uint64_t gbase,
                                                  int I, int J, int ks, int tid) {
    const uint32_t buf = sbase + (uint32_t)(ks & 1) * STG_BYTES;
    const uint32_t kb = (uint32_t)(ks * 128);
#pragma unroll
    for (int i = 0; i < 4; ++i) {         // A: 1024 16B chunks over 256 threads
        const int flat = i * 256 + tid, r = flat >> 3, c = flat & 7;
        const uint32_t dst = buf + (uint32_t)r * 128 + ((uint32_t)(c ^ (r & 7)) << 4);
        const uint64_t src = gbase + (((uint64_t)(I * 128 + r)) << 11) + kb + c * 16;
        cp16(dst, src);
    }
#pragma unroll
    for (int i = 0; i < 8; ++i) {         // B: 2048 chunks over 256 threads
        const int flat = i * 256 + tid, r = flat >> 3, c = flat & 7;
        const uint32_t dst = buf + A_BYTES + (uint32_t)r * 128 + ((uint32_t)(c ^ (r & 7)) << 4);
        const uint64_t src = gbase + (((uint64_t)(J * 256 + r)) << 11) + kb + c * 16;
        cp16(dst, src);
    }
    asm volatile("cp.async.commit_group;" ::: "memory");
}

// ---------------- kernel 1: 128x256 tile f16 GEMM + two-sided LSE partials ----------------
__global__ void __launch_bounds__(256, 2) tile_kernel() {
    extern __shared__ char smem[];
    __shared__ float rowM[512], rowS[512], colM[512], colS[512];
    const uint32_t sbase = smem_u32(smem);
    const int tid = threadIdx.x;
    const int lane = tid & 31, wid = tid >> 5;
    const int warp_m = wid & 1, warp_n = wid >> 1;     // 2 x 4 warp grid, warp tile 64x64
    const int lrow = lane & 15, lhi = lane >> 4;
    const uint32_t kx = (uint32_t)(lrow & 7);
    const uint32_t aoffA = (uint32_t)(warp_m * 64 + lrow) * 128;
    const uint32_t aoffB = A_BYTES + (uint32_t)(warp_n * 64 + lrow) * 128;

    uint64_t gbase;
    asm("cvta.to.global.u64 %0, %1;" : "=l"(gbase) : "l"(g_Hh));

    for (int t = blockIdx.x; t < NTILES; t += PGRID) {
        // decode tile index -> (I, J): tiles with I <= 2J+1, listed J-major
        int I, J;
        {
            int p = t; J = 0;
            while (p >= 2 * J + 2) { p -= 2 * J + 2; ++J; }
            I = p;
        }

        uint32_t acc[4][8][2];                 // f16x2 accumulators, 64 regs
#pragma unroll
        for (int mt = 0; mt < 4; ++mt)
#pragma unroll
            for (int nt = 0; nt < 8; ++nt) { acc[mt][nt][0] = 0u; acc[mt][nt][1] = 0u; }

        load_stage(sbase, gbase, I, J, 0, tid);

        for (int ks = 0; ks < KSTAGES; ++ks) {
            asm volatile("cp.async.wait_group 0;" ::: "memory");
            __syncthreads();   // stage ks visible; prior stage fully consumed
            if (ks + 1 < KSTAGES) load_stage(sbase, gbase, I, J, ks + 1, tid);

            const uint32_t sb = sbase + (uint32_t)(ks & 1) * STG_BYTES;
#pragma unroll
            for (int s = 0; s < 4; ++s) {                  // 4 x k16 within the 64-half stage
                const uint32_t co = (((uint32_t)(2 * s + lhi) ^ kx) << 4);
                uint32_t a[4][4], b[4][4];
#pragma unroll
                for (int mt = 0; mt < 4; ++mt)
                    ldsm4(sb + aoffA + mt * 2048 + co, a[mt][0], a[mt][1], a[mt][2], a[mt][3]);
#pragma unroll
                for (int p = 0; p < 4; ++p)
                    ldsm4(sb + aoffB + p * 2048 + co, b[p][0], b[p][1], b[p][2], b[p][3]);
#pragma unroll
                for (int mt = 0; mt < 4; ++mt)
#pragma unroll
                    for (int p = 0; p < 4; ++p) {
                        mma16816h(acc[mt][p * 2 + 0], a[mt], b[p][0], b[p][2]);
                        mma16816h(acc[mt][p * 2 + 1], a[mt], b[p][1], b[p][3]);
                    }
            }
        }

        // ---- diagonal masking (crossing tiles) and pos capture (partner tiles) ----
        // both live at cl == rl + 128*(I&1)
        const bool isCross = ((I >> 1) == J);
        const bool isPart  = (J == (I >> 1) + 32);
        if (isCross || isPart) {
            const int off = (I & 1) << 7;
#pragma unroll
            for (int mt = 0; mt < 4; ++mt)
#pragma unroll
                for (int nt = 0; nt < 8; ++nt)
#pragma unroll
                    for (int h = 0; h < 2; ++h) {
                        const int rl = warp_m * 64 + mt * 16 + h * 8 + (lane >> 2);
                        const int cl0 = warp_n * 64 + nt * 8 + (lane & 3) * 2;
                        const int tgt = rl + off;
                        __half2 pv = *(__half2*)&acc[mt][nt][h];
                        if (isPart) {
                            const int r = I * 128 + rl;
                            if (cl0 == tgt) {
                                const float v = __low2float(pv);
                                g_pos[r] = v; g_pos[r + C_NUM] = v;
                            }
                            if (cl0 + 1 == tgt) {
                                const float v = __high2float(pv);
                                g_pos[r] = v; g_pos[r + C_NUM] = v;
                            }
                        } else {   // crossing: mask diagonal
                            if (cl0 == tgt)
                                pv = __halves2half2(__float2half(-60000.f), __high2half(pv));
                            if (cl0 + 1 == tgt)
                                pv = __halves2half2(__low2half(pv), __float2half(-60000.f));
                            *(__half2*)&acc[mt][nt][h] = pv;
                        }
                    }
        }

        // ---- row-side: rows of block I over the 256 cols of block J ----
#pragma unroll
        for (int mt = 0; mt < 4; ++mt)
#pragma unroll
            for (int h = 0; h < 2; ++h) {
                float v[16];
#pragma unroll
                for (int nt = 0; nt < 8; ++nt) {
                    const __half2 pv = *(const __half2*)&acc[mt][nt][h];
                    v[2 * nt] = __low2float(pv); v[2 * nt + 1] = __high2float(pv);
                }
                float vm = v[0];
#pragma unroll
                for (int q = 1; q < 16; ++q) vm = fmaxf(vm, v[q]);
                vm = fmaxf(vm, __shfl_xor_sync(0xffffffffu, vm, 1));
                vm = fmaxf(vm, __shfl_xor_sync(0xffffffffu, vm, 2));
                float s = 0.f;
#pragma unroll
                for (int q = 0; q < 16; ++q) s += ex2f(v[q] - vm);
                s += __shfl_xor_sync(0xffffffffu, s, 1);
                s += __shfl_xor_sync(0xffffffffu, s, 2);
                if ((lane & 3) == 0) {
                    const int rl = warp_m * 64 + mt * 16 + h * 8 + (lane >> 2);
                    rowM[rl * 4 + warp_n] = vm;
                    rowS[rl * 4 + warp_n] = s;
                }
            }

        // ---- col-side: the 256 cols of J as rows, over the 128 cols of I (non-crossing) ----
        if (!isCross) {
#pragma unroll
            for (int nt = 0; nt < 8; ++nt)
#pragma unroll
                for (int i = 0; i < 2; ++i) {
                    float v[8];
#pragma unroll
                    for (int mt = 0; mt < 4; ++mt)
#pragma unroll
                        for (int h = 0; h < 2; ++h) {
                            const __half2 pv = *(const __half2*)&acc[mt][nt][h];
                            v[mt * 2 + h] = i ? __high2float(pv) : __low2float(pv);
                        }
                    float vm = v[0];
#pragma unroll
                    for (int q = 1; q < 8; ++q) vm = fmaxf(vm, v[q]);
                    vm = fmaxf(vm, __shfl_xor_sync(0xffffffffu, vm, 4));
                    vm = fmaxf(vm, __shfl_xor_sync(0xffffffffu, vm, 8));
                    vm = fmaxf(vm, __shfl_xor_sync(0xffffffffu, vm, 16));
                    float s = 0.f;
#pragma unroll
                    for (int q = 0; q < 8; ++q) s += ex2f(v[q] - vm);
                    s += __shfl_xor_sync(0xffffffffu, s, 4);
                    s += __shfl_xor_sync(0xffffffffu, s, 8);
                    s += __shfl_xor_sync(0xffffffffu, s, 16);
                    if (lane < 4) {
                        const int cl = warp_n * 64 + nt * 8 + lane * 2 + i;
                        colM[cl * 2 + warp_m] = vm;
                        colS[cl * 2 + warp_m] = s;
                    }
                }
        }
        __syncthreads();

        if (tid < 128) {   // row-side store: slot J, rows I*128..+127
            float M = -1e30f;
#pragma unroll
            for (int g = 0; g < 4; ++g) M = fmaxf(M, rowM[tid * 4 + g]);
            float S = 0.f;
#pragma unroll
            for (int g = 0; g < 4; ++g) S += rowS[tid * 4 + g] * ex2f(rowM[tid * 4 + g] - M);
            g_pm[(size_t)J * N_TOT + I * 128 + tid] = M;
            g_ps[(size_t)J * N_TOT + I * 128 + tid] = S;
        }
        if (!isCross) {    // col-side store: slot 64+I, rows J*256..+255
            const float m0 = colM[tid * 2], m1 = colM[tid * 2 + 1];
            const float M = fmaxf(m0, m1);
            const float S = colS[tid * 2] * ex2f(m0 - M) + colS[tid * 2 + 1] * ex2f(m1 - M);
            g_pm[(size_t)(64 + I) * N_TOT + J * 256 + tid] = M;
            g_ps[(size_t)(64 + I) * N_TOT + J * 256 + tid] = S;
        }
        // next loop iteration's 16 mainloop barriers separate these scratch reads
        // from the next tile's epilogue writes
    }
}

// ---------------- kernel 2: merge valid slots per row -> per-block loss partial ----------------
__global__ void merge_kernel() {
    __shared__ double red[128];
    const int r = blockIdx.x * 128 + threadIdx.x;
    const int I = r >> 7, Ih = I >> 1;
    float M = -1e30f, S = 0.f;
    for (int J = Ih; J < NCOLB; ++J) {            // row-side slots
        const float m  = g_pm[(size_t)J * N_TOT + r];
        const float sv = g_ps[(size_t)J * N_TOT + r];
        const float Mn = fmaxf(M, m);
        S = S * ex2f(M - Mn) + sv * ex2f(m - Mn);
        M = Mn;
    }
    for (int I2 = 0; I2 < 2 * Ih; ++I2) {         // col-side slots
        const float m  = g_pm[(size_t)(64 + I2) * N_TOT + r];
        const float sv = g_ps[(size_t)(64 + I2) * N_TOT + r];
        const float Mn = fmaxf(M, m);
        S = S * ex2f(M - Mn) + sv * ex2f(m - Mn);
        M = Mn;
    }
    red[threadIdx.x] = ((double)M + (double)lg2f(S) - (double)g_pos[r]) * LN2_D;
    __syncthreads();
    if (threadIdx.x == 0) {
        double s = 0.0;
        for (int i = 0; i < 128; ++i) s += red[i];
        g_partial[blockIdx.x] = s;
    }
}

// ---------------- kernel 3: final scalar (parallel reduce) ----------------
__global__ void finalize_kernel(float* out) {
    __shared__ double red[128];
    red[threadIdx.x] = g_partial[threadIdx.x];
    __syncthreads();
#pragma unroll
    for (int off = 64; off > 0; off >>= 1) {
        if (threadIdx.x < off) red[threadIdx.x] += red[threadIdx.x + off];
        __syncthreads();
    }
    if (threadIdx.x == 0) out[0] = (float)(red[0] / (double)N_TOT);
}

// ---------------- launch ----------------
extern "C" void kernel_launch(void* const* d_in, const int* in_sizes, int n_in,
                              void* d_out, int out_size) {
    const float* hi = (const float*)d_in[0];
    const float* hj = (const float*)d_in[1];
    float* out = (float*)d_out;

    dim3 cg(N_TOT / 32, D_DIM / 32), cb(32, 8);
    convert_kernel<<<cg, cb>>>(hi, hj);

    cudaFuncSetAttribute(tile_kernel, cudaFuncAttributeMaxDynamicSharedMemorySize, SMEM_TOTAL);
    tile_kernel<<<PGRID, 256, SMEM_TOTAL>>>();

    merge_kernel<<<NBLK, 128>>>();
    finalize_kernel<<<1, 128>>>(out);
}

// round 14
// speedup vs baseline: 1.1996x; 1.1996x over previous
#include <cuda_runtime.h>
#include <cuda_fp16.h>
#include <cstdint>

// ---------------- problem constants ----------------
#define D_DIM   1024
#define C_NUM   8192
#define N_TOT   16384
#define NBLK    128                      // row blocks of 128
#define NCOLB   64                       // col blocks of 256
#define NTILES  4160                     // tiles (I,J) with I <= 2J+1
#define NSLOT   190                      // 64 row-side + 126 col-side slots
#define KSTAGES 16                       // K = 1024 = 16 x 64 halves (128 B/row/stage)
#define A_BYTES (128 * 128)              // 16 KB (A: 128 rows x 64 f16)
#define B_BYTES (256 * 128)              // 32 KB (B: 256 rows x 64 f16)
#define STG_BYTES (A_BYTES + B_BYTES)    // 48 KB
#define SMEM_TOTAL (2 * STG_BYTES)       // 96 KB -> 2 CTAs/SM

#define H_SCALE 1.6986436005760381f      // sqrt(log2(e)/T), T=0.5 -> log2 domain
#define LN2_D   0.6931471805599453

// ---------------- device scratch (no allocs allowed) ----------------
// stage-major, pre-swizzled: byte = ((ks*16384 + n) * 128) + ((c ^ (n&7))*16 + e*2)
__device__ __align__(16) uint8_t g_Hs[(size_t)KSTAGES * N_TOT * 128];   // 32 MB
__device__ float  g_pm[(size_t)NSLOT * N_TOT];              // [slot][row] max
__device__ float  g_ps[(size_t)NSLOT * N_TOT];              // [slot][row] sum
__device__ float  g_pos[N_TOT];
__device__ double g_partial[NBLK];

// ---------------- PTX helpers ----------------
static __device__ __forceinline__ uint32_t smem_u32(const void* p) {
    uint32_t a;
    asm("{ .reg .u64 t; cvta.to.shared.u64 t, %1; cvt.u32.u64 %0, t; }" : "=r"(a) : "l"(p));
    return a;
}
static __device__ __forceinline__ float ex2f(float x) {
    float y; asm("ex2.approx.ftz.f32 %0, %1;" : "=f"(y) : "f"(x)); return y;
}
static __device__ __forceinline__ float lg2f(float x) {
    float y; asm("lg2.approx.f32 %0, %1;" : "=f"(y) : "f"(x)); return y;
}
static __device__ __forceinline__ void ldsm4(uint32_t a, uint32_t& r0, uint32_t& r1,
                                             uint32_t& r2, uint32_t& r3) {
    asm volatile("ldmatrix.sync.aligned.m8n8.x4.shared.b16 {%0,%1,%2,%3}, [%4];"
                 : "=r"(r0), "=r"(r1), "=r"(r2), "=r"(r3) : "r"(a));
}
// f16 inputs, f16 accumulate
static __device__ __forceinline__ void mma16816h(uint32_t* d, const uint32_t* a,
                                                 uint32_t b0, uint32_t b1) {
    asm volatile(
        "mma.sync.aligned.m16n8k16.row.col.f16.f16.f16.f16 "
        "{%0,%1}, {%2,%3,%4,%5}, {%6,%7}, {%0,%1};"
        : "+r"(d[0]), "+r"(d[1])
        : "r"(a[0]), "r"(a[1]), "r"(a[2]), "r"(a[3]), "r"(b0), "r"(b1));
}
static __device__ __forceinline__ void mbar_init(uint32_t a, uint32_t cnt) {
    asm volatile("mbarrier.init.shared.b64 [%0], %1;" :: "r"(a), "r"(cnt) : "memory");
}
static __device__ __forceinline__ void mbar_wait(uint32_t a, uint32_t parity) {
    asm volatile(
        "{\n\t.reg .pred P;\n\t"
        "WL_%=:\n\t"
        "mbarrier.try_wait.parity.acquire.cta.shared::cta.b64 P, [%0], %1, 0x989680;\n\t"
        "@!P bra WL_%=;\n\t"
        "}"
        :: "r"(a), "r"(parity) : "memory");
}
// single-thread: arm mbarrier with 48KB and issue both bulk copies for one stage
static __device__ __forceinline__ void load_stage_bulk(uint32_t dstA, uint64_t gbase,
                                                       int I, int J, int ks, uint32_t mbar) {
    const uint64_t stage = ((uint64_t)ks << 14);
    const uint64_t srcA = gbase + ((stage + ((uint64_t)I << 7)) << 7);
    const uint64_t srcB = gbase + ((stage + ((uint64_t)J << 8)) << 7);
    asm volatile("mbarrier.arrive.expect_tx.shared.b64 _, [%0], %1;"
                 :: "r"(mbar), "r"(49152u) : "memory");
    asm volatile("cp.async.bulk.shared::cluster.global.mbarrier::complete_tx::bytes "
                 "[%0], [%1], %2, [%3];"
                 :: "r"(dstA), "l"(srcA), "r"(16384u), "r"(mbar) : "memory");
    asm volatile("cp.async.bulk.shared::cluster.global.mbarrier::complete_tx::bytes "
                 "[%0], [%1], %2, [%3];"
                 :: "r"(dstA + A_BYTES), "l"(srcB), "r"(32768u), "r"(mbar) : "memory");
}

// ---------------- kernel 0: transpose + scale + f16 convert into stage-major layout ----------------
__global__ void convert_kernel(const float* __restrict__ hi, const float* __restrict__ hj) {
    __shared__ float tile[32][33];
    const int tn = blockIdx.x, td = blockIdx.y;
    const int tx = threadIdx.x, ty = threadIdx.y;   // 32 x 8
    const int n0 = tn * 32, d0 = td * 32;
    const float* src = (n0 < C_NUM) ? hi : hj;
    const int nc = (n0 < C_NUM) ? n0 : (n0 - C_NUM);
#pragma unroll
    for (int k = 0; k < 32; k += 8)
        tile[ty + k][tx] = src[(size_t)(d0 + ty + k) * C_NUM + nc + tx];
    __syncthreads();
#pragma unroll
    for (int k = 0; k < 32; k += 8) {
        const float v = tile[tx][ty + k];
        const int n = n0 + ty + k, d = d0 + tx;
        const int ks = d >> 6, c = (d >> 3) & 7, e = d & 7;
        const size_t off = (((size_t)(ks << 14) + (size_t)n) << 7)
                         + (uint32_t)(((c ^ (n & 7)) << 4) + (e << 1));
        *(__half*)(g_Hs + off) = __float2half(v * H_SCALE);
    }
}

// ---------------- kernel 1: 128x256 tile f16 GEMM + two-sided LSE partials ----------------
__global__ void __launch_bounds__(256, 2) tile_kernel() {
    extern __shared__ char smem[];
    __shared__ float rowM[512], rowS[512], colM[512], colS[512];
    __shared__ __align__(8) uint64_t mbars[2];
    const uint32_t sbase = smem_u32(smem);
    const uint32_t mb0 = smem_u32(mbars), mb1 = mb0 + 8;
    const int tid = threadIdx.x;
    const int lane = tid & 31, wid = tid >> 5;
    const int warp_m = wid & 1, warp_n = wid >> 1;     // 2 x 4 warp grid, warp tile 64x64
    const int lrow = lane & 15, lhi = lane >> 4;
    const uint32_t kx = (uint32_t)(lrow & 7);
    const uint32_t aoffA = (uint32_t)(warp_m * 64 + lrow) * 128;
    const uint32_t aoffB = A_BYTES + (uint32_t)(warp_n * 64 + lrow) * 128;

    // decode tile index -> (I, J): tiles with I <= 2J+1, listed J-major
    int I, J;
    {
        int p = blockIdx.x; J = 0;
        while (p >= 2 * J + 2) { p -= 2 * J + 2; ++J; }
        I = p;
    }

    uint64_t gbase;
    asm("cvta.to.global.u64 %0, %1;" : "=l"(gbase) : "l"(g_Hs));

    if (tid == 0) { mbar_init(mb0, 1); mbar_init(mb1, 1); }
    __syncthreads();
    if (tid == 0) load_stage_bulk(sbase, gbase, I, J, 0, mb0);

    uint32_t acc[4][8][2];                 // f16x2 accumulators, 64 regs
#pragma unroll
    for (int mt = 0; mt < 4; ++mt)
#pragma unroll
        for (int nt = 0; nt < 8; ++nt) { acc[mt][nt][0] = 0u; acc[mt][nt][1] = 0u; }

    for (int ks = 0; ks < KSTAGES; ++ks) {
        mbar_wait((ks & 1) ? mb1 : mb0, (uint32_t)((ks >> 1) & 1));
        __syncthreads();   // all warps done computing stage ks-1 -> other buffer reusable
        if (tid == 0 && ks + 1 < KSTAGES)
            load_stage_bulk(sbase + (uint32_t)((ks + 1) & 1) * STG_BYTES, gbase, I, J,
                            ks + 1, ((ks + 1) & 1) ? mb1 : mb0);

        const uint32_t sb = sbase + (uint32_t)(ks & 1) * STG_BYTES;
#pragma unroll
        for (int s = 0; s < 4; ++s) {                  // 4 x k16 within the 64-half stage
            const uint32_t co = (((uint32_t)(2 * s + lhi) ^ kx) << 4);
            uint32_t a[4][4], b[4][4];
#pragma unroll
            for (int mt = 0; mt < 4; ++mt)
                ldsm4(sb + aoffA + mt * 2048 + co, a[mt][0], a[mt][1], a[mt][2], a[mt][3]);
#pragma unroll
            for (int p = 0; p < 4; ++p)
                ldsm4(sb + aoffB + p * 2048 + co, b[p][0], b[p][1], b[p][2], b[p][3]);
#pragma unroll
            for (int mt = 0; mt < 4; ++mt)
#pragma unroll
                for (int p = 0; p < 4; ++p) {
                    mma16816h(acc[mt][p * 2 + 0], a[mt], b[p][0], b[p][2]);
                    mma16816h(acc[mt][p * 2 + 1], a[mt], b[p][1], b[p][3]);
                }
        }
    }

    // ---- diagonal masking (crossing tiles) and pos capture (partner tiles) ----
    // both live at cl == rl + 128*(I&1)
    const bool isCross = ((I >> 1) == J);
    const bool isPart  = (J == (I >> 1) + 32);
    if (isCross || isPart) {
        const int off = (I & 1) << 7;
#pragma unroll
        for (int mt = 0; mt < 4; ++mt)
#pragma unroll
            for (int nt = 0; nt < 8; ++nt)
#pragma unroll
                for (int h = 0; h < 2; ++h) {
                    const int rl = warp_m * 64 + mt * 16 + h * 8 + (lane >> 2);
                    const int cl0 = warp_n * 64 + nt * 8 + (lane & 3) * 2;
                    const int tgt = rl + off;
                    __half2 pv = *(__half2*)&acc[mt][nt][h];
                    if (isPart) {
                        const int r = I * 128 + rl;
                        if (cl0 == tgt) {
                            const float v = __low2float(pv);
                            g_pos[r] = v; g_pos[r + C_NUM] = v;
                        }
                        if (cl0 + 1 == tgt) {
                            const float v = __high2float(pv);
                            g_pos[r] = v; g_pos[r + C_NUM] = v;
                        }
                    } else {   // crossing: mask diagonal
                        if (cl0 == tgt)
                            pv = __halves2half2(__float2half(-60000.f), __high2half(pv));
                        if (cl0 + 1 == tgt)
                            pv = __halves2half2(__low2half(pv), __float2half(-60000.f));
                        *(__half2*)&acc[mt][nt][h] = pv;
                    }
                }
    }

    // ---- row-side: rows of block I over the 256 cols of block J ----
#pragma unroll
    for (int mt = 0; mt < 4; ++mt)
#pragma unroll
        for (int h = 0; h < 2; ++h) {
            float v[16];
#pragma unroll
            for (int nt = 0; nt < 8; ++nt) {
                const __half2 pv = *(const __half2*)&acc[mt][nt][h];
                v[2 * nt] = __low2float(pv); v[2 * nt + 1] = __high2float(pv);
            }
            float vm = v[0];
#pragma unroll
            for (int q = 1; q < 16; ++q) vm = fmaxf(vm, v[q]);
            vm = fmaxf(vm, __shfl_xor_sync(0xffffffffu, vm, 1));
            vm = fmaxf(vm, __shfl_xor_sync(0xffffffffu, vm, 2));
            float s = 0.f;
#pragma unroll
            for (int q = 0; q < 16; ++q) s += ex2f(v[q] - vm);
            s += __shfl_xor_sync(0xffffffffu, s, 1);
            s += __shfl_xor_sync(0xffffffffu, s, 2);
            if ((lane & 3) == 0) {
                const int rl = warp_m * 64 + mt * 16 + h * 8 + (lane >> 2);
                rowM[rl * 4 + warp_n] = vm;
                rowS[rl * 4 + warp_n] = s;
            }
        }

    // ---- col-side: the 256 cols of J as rows, over the 128 cols of I (non-crossing) ----
    if (!isCross) {
#pragma unroll
        for (int nt = 0; nt < 8; ++nt)
#pragma unroll
            for (int i = 0; i < 2; ++i) {
                float v[8];
#pragma unroll
                for (int mt = 0; mt < 4; ++mt)
#pragma unroll
                    for (int h = 0; h < 2; ++h) {
                        const __half2 pv = *(const __half2*)&acc[mt][nt][h];
                        v[mt * 2 + h] = i ? __high2float(pv) : __low2float(pv);
                    }
                float vm = v[0];
#pragma unroll
                for (int q = 1; q < 8; ++q) vm = fmaxf(vm, v[q]);
                vm = fmaxf(vm, __shfl_xor_sync(0xffffffffu, vm, 4));
                vm = fmaxf(vm, __shfl_xor_sync(0xffffffffu, vm, 8));
                vm = fmaxf(vm, __shfl_xor_sync(0xffffffffu, vm, 16));
                float s = 0.f;
#pragma unroll
                for (int q = 0; q < 8; ++q) s += ex2f(v[q] - vm);
                s += __shfl_xor_sync(0xffffffffu, s, 4);
                s += __shfl_xor_sync(0xffffffffu, s, 8);
                s += __shfl_xor_sync(0xffffffffu, s, 16);
                if (lane < 4) {
                    const int cl = warp_n * 64 + nt * 8 + lane * 2 + i;
                    colM[cl * 2 + warp_m] = vm;
                    colS[cl * 2 + warp_m] = s;
                }
            }
    }
    __syncthreads();

    if (tid < 128) {   // row-side store: slot J, rows I*128..+127
        float M = -1e30f;
#pragma unroll
        for (int g = 0; g < 4; ++g) M = fmaxf(M, rowM[tid * 4 + g]);
        float S = 0.f;
#pragma unroll
        for (int g = 0; g < 4; ++g) S += rowS[tid * 4 + g] * ex2f(rowM[tid * 4 + g] - M);
        g_pm[(size_t)J * N_TOT + I * 128 + tid] = M;
        g_ps[(size_t)J * N_TOT + I * 128 + tid] = S;
    }
    if (!isCross) {    // col-side store: slot 64+I, rows J*256..+255
        const float m0 = colM[tid * 2], m1 = colM[tid * 2 + 1];
        const float M = fmaxf(m0, m1);
        const float S = colS[tid * 2] * ex2f(m0 - M) + colS[tid * 2 + 1] * ex2f(m1 - M);
        g_pm[(size_t)(64 + I) * N_TOT + J * 256 + tid] = M;
        g_ps[(size_t)(64 + I) * N_TOT + J * 256 + tid] = S;
    }
}

// ---------------- kernel 2: merge valid slots per row -> per-block loss partial ----------------
__global__ void merge_kernel() {
    __shared__ double red[128];
    const int r = blockIdx.x * 128 + threadIdx.x;
    const int I = r >> 7, Ih = I >> 1;
    float M = -1e30f, S = 0.f;
    for (int J = Ih; J < NCOLB; ++J) {            // row-side slots
        const float m  = g_pm[(size_t)J * N_TOT + r];
        const float sv = g_ps[(size_t)J * N_TOT + r];
        const float Mn = fmaxf(M, m);
        S = S * ex2f(M - Mn) + sv * ex2f(m - Mn);
        M = Mn;
    }
    for (int I2 = 0; I2 < 2 * Ih; ++I2) {         // col-side slots
        const float m  = g_pm[(size_t)(64 + I2) * N_TOT + r];
        const float sv = g_ps[(size_t)(64 + I2) * N_TOT + r];
        const float Mn = fmaxf(M, m);
        S = S * ex2f(M - Mn) + sv * ex2f(m - Mn);
        M = Mn;
    }
    red[threadIdx.x] = ((double)M + (double)lg2f(S) - (double)g_pos[r]) * LN2_D;
    __syncthreads();
    if (threadIdx.x == 0) {
        double s = 0.0;
        for (int i = 0; i < 128; ++i) s += red[i];
        g_partial[blockIdx.x] = s;
    }
}

// ---------------- kernel 3: final scalar (parallel reduce) ----------------
__global__ void finalize_kernel(float* out) {
    __shared__ double red[128];
    red[threadIdx.x] = g_partial[threadIdx.x];
    __syncthreads();
#pragma unroll
    for (int off = 64; off > 0; off >>= 1) {
        if (threadIdx.x < off) red[threadIdx.x] += red[threadIdx.x + off];
        __syncthreads();
    }
    if (threadIdx.x == 0) out[0] = (float)(red[0] / (double)N_TOT);
}

// ---------------- launch ----------------
extern "C" void kernel_launch(void* const* d_in, const int* in_sizes, int n_in,
                              void* d_out, int out_size) {
    const float* hi = (const float*)d_in[0];
    const float* hj = (const float*)d_in[1];
    float* out = (float*)d_out;

    dim3 cg(N_TOT / 32, D_DIM / 32), cb(32, 8);
    convert_kernel<<<cg, cb>>>(hi, hj);

    cudaFuncSetAttribute(tile_kernel, cudaFuncAttributeMaxDynamicSharedMemorySize, SMEM_TOTAL);
    tile_kernel<<<NTILES, 256, SMEM_TOTAL>>>();

    merge_kernel<<<NBLK, 128>>>();
    finalize_kernel<<<1, 128>>>(out);
}

// round 15
// speedup vs baseline: 1.2184x; 1.0157x over previous
#include <cuda_runtime.h>
#include <cuda_fp16.h>
#include <cstdint>

// ---------------- problem constants ----------------
#define D_DIM   1024
#define C_NUM   8192
#define N_TOT   16384
#define NBLK    128                      // row blocks of 128
#define NCOLB   64                       // col blocks of 256
#define NTILES  4160                     // tiles (I,J) with I <= 2J+1
#define NSLOT   190                      // 64 row-side + 126 col-side slots
#define KSTAGES 16                       // K = 1024 = 16 x 64 halves (128 B/row/stage)
#define A_BYTES (128 * 128)              // 16 KB (A: 128 rows x 64 f16)
#define B_BYTES (256 * 128)              // 32 KB (B: 256 rows x 64 f16)
#define STG_BYTES (A_BYTES + B_BYTES)    // 48 KB
#define SMEM_TOTAL (2 * STG_BYTES)       // 96 KB -> 2 CTAs/SM

#define H_SCALE 1.6986436005760381f      // sqrt(log2(e)/T), T=0.5 -> log2 domain
#define LN2_D   0.6931471805599453

// ---------------- device scratch (no allocs allowed) ----------------
// stage-major, pre-swizzled: byte = ((ks*16384 + n) * 128) + ((c ^ (n&7))*16 + e*2)
__device__ __align__(16) uint8_t g_Hs[(size_t)KSTAGES * N_TOT * 128];   // 32 MB
__device__ float  g_pm[(size_t)NSLOT * N_TOT];              // [slot][row] max
__device__ float  g_ps[(size_t)NSLOT * N_TOT];              // [slot][row] sum
__device__ float  g_pos[N_TOT];
__device__ double g_partial[NBLK];

// ---------------- PTX helpers ----------------
static __device__ __forceinline__ uint32_t smem_u32(const void* p) {
    uint32_t a;
    asm("{ .reg .u64 t; cvta.to.shared.u64 t, %1; cvt.u32.u64 %0, t; }" : "=r"(a) : "l"(p));
    return a;
}
static __device__ __forceinline__ float ex2f(float x) {
    float y; asm("ex2.approx.ftz.f32 %0, %1;" : "=f"(y) : "f"(x)); return y;
}
static __device__ __forceinline__ float lg2f(float x) {
    float y; asm("lg2.approx.f32 %0, %1;" : "=f"(y) : "f"(x)); return y;
}
static __device__ __forceinline__ void ldsm4(uint32_t a, uint32_t& r0, uint32_t& r1,
                                             uint32_t& r2, uint32_t& r3) {
    asm volatile("ldmatrix.sync.aligned.m8n8.x4.shared.b16 {%0,%1,%2,%3}, [%4];"
                 : "=r"(r0), "=r"(r1), "=r"(r2), "=r"(r3) : "r"(a));
}
// f16 inputs, f16 accumulate
static __device__ __forceinline__ void mma16816h(uint32_t* d, const uint32_t* a,
                                                 uint32_t b0, uint32_t b1) {
    asm volatile(
        "mma.sync.aligned.m16n8k16.row.col.f16.f16.f16.f16 "
        "{%0,%1}, {%2,%3,%4,%5}, {%6,%7}, {%0,%1};"
        : "+r"(d[0]), "+r"(d[1])
        : "r"(a[0]), "r"(a[1]), "r"(a[2]), "r"(a[3]), "r"(b0), "r"(b1));
}
static __device__ __forceinline__ void mbar_init(uint32_t a, uint32_t cnt) {
    asm volatile("mbarrier.init.shared.b64 [%0], %1;" :: "r"(a), "r"(cnt) : "memory");
}
static __device__ __forceinline__ void mbar_arrive(uint32_t a) {
    asm volatile("mbarrier.arrive.shared.b64 _, [%0];" :: "r"(a) : "memory");
}
static __device__ __forceinline__ void mbar_wait(uint32_t a, uint32_t parity) {
    asm volatile(
        "{\n\t.reg .pred P;\n\t"
        "WL_%=:\n\t"
        "mbarrier.try_wait.parity.acquire.cta.shared::cta.b64 P, [%0], %1, 0x989680;\n\t"
        "@!P bra WL_%=;\n\t"
        "}"
        :: "r"(a), "r"(parity) : "memory");
}
// single-thread: arm mbarrier with 48KB and issue both bulk copies for one stage
static __device__ __forceinline__ void load_stage_bulk(uint32_t dstA, uint64_t gbase,
                                                       int I, int J, int ks, uint32_t mbar) {
    const uint64_t stage = ((uint64_t)ks << 14);
    const uint64_t srcA = gbase + ((stage + ((uint64_t)I << 7)) << 7);
    const uint64_t srcB = gbase + ((stage + ((uint64_t)J << 8)) << 7);
    asm volatile("mbarrier.arrive.expect_tx.shared.b64 _, [%0], %1;"
                 :: "r"(mbar), "r"(49152u) : "memory");
    asm volatile("cp.async.bulk.shared::cluster.global.mbarrier::complete_tx::bytes "
                 "[%0], [%1], %2, [%3];"
                 :: "r"(dstA), "l"(srcA), "r"(16384u), "r"(mbar) : "memory");
    asm volatile("cp.async.bulk.shared::cluster.global.mbarrier::complete_tx::bytes "
                 "[%0], [%1], %2, [%3];"
                 :: "r"(dstA + A_BYTES), "l"(srcB), "r"(32768u), "r"(mbar) : "memory");
}

// ---------------- kernel 0: transpose + scale + f16 convert into stage-major layout ----------------
__global__ void convert_kernel(const float* __restrict__ hi, const float* __restrict__ hj) {
    __shared__ float tile[32][33];
    const int tn = blockIdx.x, td = blockIdx.y;
    const int tx = threadIdx.x, ty = threadIdx.y;   // 32 x 8
    const int n0 = tn * 32, d0 = td * 32;
    const float* src = (n0 < C_NUM) ? hi : hj;
    const int nc = (n0 < C_NUM) ? n0 : (n0 - C_NUM);
#pragma unroll
    for (int k = 0; k < 32; k += 8)
        tile[ty + k][tx] = src[(size_t)(d0 + ty + k) * C_NUM + nc + tx];
    __syncthreads();
#pragma unroll
    for (int k = 0; k < 32; k += 8) {
        const float v = tile[tx][ty + k];
        const int n = n0 + ty + k, d = d0 + tx;
        const int ks = d >> 6, c = (d >> 3) & 7, e = d & 7;
        const size_t off = (((size_t)(ks << 14) + (size_t)n) << 7)
                         + (uint32_t)(((c ^ (n & 7)) << 4) + (e << 1));
        *(__half*)(g_Hs + off) = __float2half(v * H_SCALE);
    }
}

// ---------------- kernel 1: 128x256 tile f16 GEMM + two-sided LSE partials ----------------
__global__ void __launch_bounds__(256, 2) tile_kernel() {
    extern __shared__ char smem[];
    __shared__ float rowM[512], rowS[512], colM[512], colS[512];
    __shared__ __align__(8) uint64_t mbars[4];   // full0, full1, empty0, empty1
    const uint32_t sbase = smem_u32(smem);
    const uint32_t mfull = smem_u32(mbars), mempty = mfull + 16;
    const int tid = threadIdx.x;
    const int lane = tid & 31, wid = tid >> 5;
    const int warp_m = wid & 1, warp_n = wid >> 1;     // 2 x 4 warp grid, warp tile 64x64
    const int lrow = lane & 15, lhi = lane >> 4;
    const uint32_t kx = (uint32_t)(lrow & 7);
    const uint32_t aoffA = (uint32_t)(warp_m * 64 + lrow) * 128;
    const uint32_t aoffB = A_BYTES + (uint32_t)(warp_n * 64 + lrow) * 128;

    // decode tile index -> (I, J): tiles with I <= 2J+1, listed J-major
    int I, J;
    {
        int p = blockIdx.x; J = 0;
        while (p >= 2 * J + 2) { p -= 2 * J + 2; ++J; }
        I = p;
    }

    uint64_t gbase;
    asm("cvta.to.global.u64 %0, %1;" : "=l"(gbase) : "l"(g_Hs));

    if (tid == 0) {
        mbar_init(mfull, 1);      mbar_init(mfull + 8, 1);
        mbar_init(mempty, 256);   mbar_init(mempty + 8, 256);
    }
    __syncthreads();
    if (tid == 0) {
        load_stage_bulk(sbase, gbase, I, J, 0, mfull);
        load_stage_bulk(sbase + STG_BYTES, gbase, I, J, 1, mfull + 8);
    }

    uint32_t acc[4][8][2];                 // f16x2 accumulators, 64 regs
#pragma unroll
    for (int mt = 0; mt < 4; ++mt)
#pragma unroll
        for (int nt = 0; nt < 8; ++nt) { acc[mt][nt][0] = 0u; acc[mt][nt][1] = 0u; }

    for (int ks = 0; ks < KSTAGES; ++ks) {
        const uint32_t b = (uint32_t)(ks & 1);
        // producer: issue stage ks+1 into the other buffer once all consumed stage ks-1
        if (tid == 0 && ks >= 1 && ks + 1 < KSTAGES) {
            const uint32_t nb = 1u - b;
            mbar_wait(mempty + nb * 8, (uint32_t)(((ks - 1) >> 1) & 1));
            load_stage_bulk(sbase + nb * STG_BYTES, gbase, I, J, ks + 1, mfull + nb * 8);
        }
        // consumer: wait stage ks data
        mbar_wait(mfull + b * 8, (uint32_t)((ks >> 1) & 1));

        const uint32_t sb = sbase + b * STG_BYTES;
#pragma unroll
        for (int s = 0; s < 4; ++s) {                  // 4 x k16 within the 64-half stage
            const uint32_t co = (((uint32_t)(2 * s + lhi) ^ kx) << 4);
            uint32_t a[4][4], bb[4][4];
#pragma unroll
            for (int mt = 0; mt < 4; ++mt)
                ldsm4(sb + aoffA + mt * 2048 + co, a[mt][0], a[mt][1], a[mt][2], a[mt][3]);
#pragma unroll
            for (int p = 0; p < 4; ++p)
                ldsm4(sb + aoffB + p * 2048 + co, bb[p][0], bb[p][1], bb[p][2], bb[p][3]);
#pragma unroll
            for (int mt = 0; mt < 4; ++mt)
#pragma unroll
                for (int p = 0; p < 4; ++p) {
                    mma16816h(acc[mt][p * 2 + 0], a[mt], bb[p][0], bb[p][2]);
                    mma16816h(acc[mt][p * 2 + 1], a[mt], bb[p][1], bb[p][3]);
                }
        }
        mbar_arrive(mempty + b * 8);       // non-blocking: signal stage ks consumed
    }

    // ---- diagonal masking (crossing tiles) and pos capture (partner tiles) ----
    // both live at cl == rl + 128*(I&1)
    const bool isCross = ((I >> 1) == J);
    const bool isPart  = (J == (I >> 1) + 32);
    if (isCross || isPart) {
        const int off = (I & 1) << 7;
#pragma unroll
        for (int mt = 0; mt < 4; ++mt)
#pragma unroll
            for (int nt = 0; nt < 8; ++nt)
#pragma unroll
                for (int h = 0; h < 2; ++h) {
                    const int rl = warp_m * 64 + mt * 16 + h * 8 + (lane >> 2);
                    const int cl0 = warp_n * 64 + nt * 8 + (lane & 3) * 2;
                    const int tgt = rl + off;
                    __half2 pv = *(__half2*)&acc[mt][nt][h];
                    if (isPart) {
                        const int r = I * 128 + rl;
                        if (cl0 == tgt) {
                            const float v = __low2float(pv);
                            g_pos[r] = v; g_pos[r + C_NUM] = v;
                        }
                        if (cl0 + 1 == tgt) {
                            const float v = __high2float(pv);
                            g_pos[r] = v; g_pos[r + C_NUM] = v;
                        }
                    } else {   // crossing: mask diagonal
                        if (cl0 == tgt)
                            pv = __halves2half2(__float2half(-60000.f), __high2half(pv));
                        if (cl0 + 1 == tgt)
                            pv = __halves2half2(__low2half(pv), __float2half(-60000.f));
                        *(__half2*)&acc[mt][nt][h] = pv;
                    }
                }
    }

    // ---- row-side: rows of block I over the 256 cols of block J ----
#pragma unroll
    for (int mt = 0; mt < 4; ++mt)
#pragma unroll
        for (int h = 0; h < 2; ++h) {
            float v[16];
#pragma unroll
            for (int nt = 0; nt < 8; ++nt) {
                const __half2 pv = *(const __half2*)&acc[mt][nt][h];
                v[2 * nt] = __low2float(pv); v[2 * nt + 1] = __high2float(pv);
            }
            float vm = v[0];
#pragma unroll
            for (int q = 1; q < 16; ++q) vm = fmaxf(vm, v[q]);
            vm = fmaxf(vm, __shfl_xor_sync(0xffffffffu, vm, 1));
            vm = fmaxf(vm, __shfl_xor_sync(0xffffffffu, vm, 2));
            float s = 0.f;
#pragma unroll
            for (int q = 0; q < 16; ++q) s += ex2f(v[q] - vm);
            s += __shfl_xor_sync(0xffffffffu, s, 1);
            s += __shfl_xor_sync(0xffffffffu, s, 2);
            if ((lane & 3) == 0) {
                const int rl = warp_m * 64 + mt * 16 + h * 8 + (lane >> 2);
                rowM[rl * 4 + warp_n] = vm;
                rowS[rl * 4 + warp_n] = s;
            }
        }

    // ---- col-side: the 256 cols of J as rows, over the 128 cols of I (non-crossing) ----
    if (!isCross) {
#pragma unroll
        for (int nt = 0; nt < 8; ++nt)
#pragma unroll
            for (int i = 0; i < 2; ++i) {
                float v[8];
#pragma unroll
                for (int mt = 0; mt < 4; ++mt)
#pragma unroll
                    for (int h = 0; h < 2; ++h) {
                        const __half2 pv = *(const __half2*)&acc[mt][nt][h];
                        v[mt * 2 + h] = i ? __high2float(pv) : __low2float(pv);
                    }
                float vm = v[0];
#pragma unroll
                for (int q = 1; q < 8; ++q) vm = fmaxf(vm, v[q]);
                vm = fmaxf(vm, __shfl_xor_sync(0xffffffffu, vm, 4));
                vm = fmaxf(vm, __shfl_xor_sync(0xffffffffu, vm, 8));
                vm = fmaxf(vm, __shfl_xor_sync(0xffffffffu, vm, 16));
                float s = 0.f;
#pragma unroll
                for (int q = 0; q < 8; ++q) s += ex2f(v[q] - vm);
                s += __shfl_xor_sync(0xffffffffu, s, 4);
                s += __shfl_xor_sync(0xffffffffu, s, 8);
                s += __shfl_xor_sync(0xffffffffu, s, 16);
                if (lane < 4) {
                    const int cl = warp_n * 64 + nt * 8 + lane * 2 + i;
                    colM[cl * 2 + warp_m] = vm;
                    colS[cl * 2 + warp_m] = s;
                }
            }
    }
    __syncthreads();

    if (tid < 128) {   // row-side store: slot J, rows I*128..+127
        float M = -1e30f;
#pragma unroll
        for (int g = 0; g < 4; ++g) M = fmaxf(M, rowM[tid * 4 + g]);
        float S = 0.f;
#pragma unroll
        for (int g = 0; g < 4; ++g) S += rowS[tid * 4 + g] * ex2f(rowM[tid * 4 + g] - M);
        g_pm[(size_t)J * N_TOT + I * 128 + tid] = M;
        g_ps[(size_t)J * N_TOT + I * 128 + tid] = S;
    }
    if (!isCross) {    // col-side store: slot 64+I, rows J*256..+255
        const float m0 = colM[tid * 2], m1 = colM[tid * 2 + 1];
        const float M = fmaxf(m0, m1);
        const float S = colS[tid * 2] * ex2f(m0 - M) + colS[tid * 2 + 1] * ex2f(m1 - M);
        g_pm[(size_t)(64 + I) * N_TOT + J * 256 + tid] = M;
        g_ps[(size_t)(64 + I) * N_TOT + J * 256 + tid] = S;
    }
}

// ---------------- kernel 2: merge valid slots per row -> per-block loss partial ----------------
__global__ void merge_kernel() {
    __shared__ double red[128];
    const int r = blockIdx.x * 128 + threadIdx.x;
    const int I = r >> 7, Ih = I >> 1;
    float M = -1e30f, S = 0.f;
    for (int J = Ih; J < NCOLB; ++J) {            // row-side slots
        const float m  = g_pm[(size_t)J * N_TOT + r];
        const float sv = g_ps[(size_t)J * N_TOT + r];
        const float Mn = fmaxf(M, m);
        S = S * ex2f(M - Mn) + sv * ex2f(m - Mn);
        M = Mn;
    }
    for (int I2 = 0; I2 < 2 * Ih; ++I2) {         // col-side slots
        const float m  = g_pm[(size_t)(64 + I2) * N_TOT + r];
        const float sv = g_ps[(size_t)(64 + I2) * N_TOT + r];
        const float Mn = fmaxf(M, m);
        S = S * ex2f(M - Mn) + sv * ex2f(m - Mn);
        M = Mn;
    }
    red[threadIdx.x] = ((double)M + (double)lg2f(S) - (double)g_pos[r]) * LN2_D;
    __syncthreads();
    if (threadIdx.x == 0) {
        double s = 0.0;
        for (int i = 0; i < 128; ++i) s += red[i];
        g_partial[blockIdx.x] = s;
    }
}

// ---------------- kernel 3: final scalar (parallel reduce) ----------------
__global__ void finalize_kernel(float* out) {
    __shared__ double red[128];
    red[threadIdx.x] = g_partial[threadIdx.x];
    __syncthreads();
#pragma unroll
    for (int off = 64; off > 0; off >>= 1) {
        if (threadIdx.x < off) red[threadIdx.x] += red[threadIdx.x + off];
        __syncthreads();
    }
    if (threadIdx.x == 0) out[0] = (float)(red[0] / (double)N_TOT);
}

// ---------------- launch ----------------
extern "C" void kernel_launch(void* const* d_in, const int* in_sizes, int n_in,
                              void* d_out, int out_size) {
    const float* hi = (const float*)d_in[0];
    const float* hj = (const float*)d_in[1];
    float* out = (float*)d_out;

    dim3 cg(N_TOT / 32, D_DIM / 32), cb(32, 8);
    convert_kernel<<<cg, cb>>>(hi, hj);

    cudaFuncSetAttribute(tile_kernel, cudaFuncAttributeMaxDynamicSharedMemorySize, SMEM_TOTAL);
    tile_kernel<<<NTILES, 256, SMEM_TOTAL>>>();

    merge_kernel<<<NBLK, 128>>>();
    finalize_kernel<<<1, 128>>>(out);
}

// round 16
// speedup vs baseline: 1.2256x; 1.0059x over previous
#include <cuda_runtime.h>
#include <cuda_fp16.h>
#include <cstdint>

// ---------------- problem constants ----------------
#define D_DIM   1024
#define C_NUM   8192
#define N_TOT   16384
#define NBLK    128                      // row blocks of 128
#define NCOLB   64                       // col blocks of 256
#define NTILES  4160                     // tiles (I,J) with I <= 2J+1
#define NSLOT   190                      // 64 row-side + 126 col-side slots
#define KSTAGES 16                       // K = 1024 = 16 x 64 halves (128 B/row/stage)
#define A_BYTES (128 * 128)              // 16 KB (A: 128 rows x 64 f16)
#define B_BYTES (256 * 128)              // 32 KB (B: 256 rows x 64 f16)
#define STG_BYTES (A_BYTES + B_BYTES)    // 48 KB
#define SMEM_TOTAL (2 * STG_BYTES)       // 96 KB -> 2 CTAs/SM

#define H_SCALE 1.6986436005760381f      // sqrt(log2(e)/T), T=0.5 -> log2 domain
#define LN2_D   0.6931471805599453

// ---------------- device scratch (no allocs allowed) ----------------
// stage-major, pre-swizzled: byte = ((ks*16384 + n) * 128) + ((c ^ (n&7))*16 + e*2)
__device__ __align__(16) uint8_t g_Hs[(size_t)KSTAGES * N_TOT * 128];   // 32 MB
__device__ float  g_pm[(size_t)NSLOT * N_TOT];              // [slot][row] max
__device__ float  g_ps[(size_t)NSLOT * N_TOT];              // [slot][row] sum
__device__ float  g_pos[N_TOT];
__device__ double g_partial[NBLK];

// ---------------- PTX helpers ----------------
static __device__ __forceinline__ uint32_t smem_u32(const void* p) {
    uint32_t a;
    asm("{ .reg .u64 t; cvta.to.shared.u64 t, %1; cvt.u32.u64 %0, t; }" : "=r"(a) : "l"(p));
    return a;
}
static __device__ __forceinline__ float ex2f(float x) {
    float y; asm("ex2.approx.ftz.f32 %0, %1;" : "=f"(y) : "f"(x)); return y;
}
static __device__ __forceinline__ float lg2f(float x) {
    float y; asm("lg2.approx.f32 %0, %1;" : "=f"(y) : "f"(x)); return y;
}
static __device__ __forceinline__ void ldsm4(uint32_t a, uint32_t& r0, uint32_t& r1,
                                             uint32_t& r2, uint32_t& r3) {
    asm volatile("ldmatrix.sync.aligned.m8n8.x4.shared.b16 {%0,%1,%2,%3}, [%4];"
                 : "=r"(r0), "=r"(r1), "=r"(r2), "=r"(r3) : "r"(a));
}
// f16 inputs, f16 accumulate
static __device__ __forceinline__ void mma16816h(uint32_t* d, const uint32_t* a,
                                                 uint32_t b0, uint32_t b1) {
    asm volatile(
        "mma.sync.aligned.m16n8k16.row.col.f16.f16.f16.f16 "
        "{%0,%1}, {%2,%3,%4,%5}, {%6,%7}, {%0,%1};"
        : "+r"(d[0]), "+r"(d[1])
        : "r"(a[0]), "r"(a[1]), "r"(a[2]), "r"(a[3]), "r"(b0), "r"(b1));
}
static __device__ __forceinline__ void mbar_init(uint32_t a, uint32_t cnt) {
    asm volatile("mbarrier.init.shared.b64 [%0], %1;" :: "r"(a), "r"(cnt) : "memory");
}
static __device__ __forceinline__ void mbar_arrive(uint32_t a) {
    asm volatile("mbarrier.arrive.shared.b64 _, [%0];" :: "r"(a) : "memory");
}
static __device__ __forceinline__ void mbar_wait(uint32_t a, uint32_t parity) {
    asm volatile(
        "{\n\t.reg .pred P;\n\t"
        "WL_%=:\n\t"
        "mbarrier.try_wait.parity.acquire.cta.shared::cta.b64 P, [%0], %1, 0x989680;\n\t"
        "@!P bra WL_%=;\n\t"
        "}"
        :: "r"(a), "r"(parity) : "memory");
}
// relaxed wait: producer-only (post-wait accesses are async-proxy bulk copies)
static __device__ __forceinline__ void mbar_wait_relaxed(uint32_t a, uint32_t parity) {
    asm volatile(
        "{\n\t.reg .pred P;\n\t"
        "WL_%=:\n\t"
        "mbarrier.try_wait.parity.relaxed.cta.shared::cta.b64 P, [%0], %1, 0x989680;\n\t"
        "@!P bra WL_%=;\n\t"
        "}"
        :: "r"(a), "r"(parity) : "memory");
}
// single-thread: arm mbarrier with 48KB and issue both bulk copies for one stage
static __device__ __forceinline__ void load_stage_bulk(uint32_t dstA, uint64_t gbase,
                                                       int I, int J, int ks, uint32_t mbar) {
    const uint64_t stage = ((uint64_t)ks << 14);
    const uint64_t srcA = gbase + ((stage + ((uint64_t)I << 7)) << 7);
    const uint64_t srcB = gbase + ((stage + ((uint64_t)J << 8)) << 7);
    asm volatile("mbarrier.arrive.expect_tx.shared.b64 _, [%0], %1;"
                 :: "r"(mbar), "r"(49152u) : "memory");
    asm volatile("cp.async.bulk.shared::cluster.global.mbarrier::complete_tx::bytes "
                 "[%0], [%1], %2, [%3];"
                 :: "r"(dstA), "l"(srcA), "r"(16384u), "r"(mbar) : "memory");
    asm volatile("cp.async.bulk.shared::cluster.global.mbarrier::complete_tx::bytes "
                 "[%0], [%1], %2, [%3];"
                 :: "r"(dstA + A_BYTES), "l"(srcB), "r"(32768u), "r"(mbar) : "memory");
}

// ---------------- kernel 0: transpose + scale + f16 convert, 16B coalesced stores ----------------
// block: 32 n-rows x 64 d-cols (one full K-stage of d per block row)
__global__ void convert_kernel(const float* __restrict__ hi, const float* __restrict__ hj) {
    __shared__ float tile[64][33];
    const int tn = blockIdx.x, td = blockIdx.y;     // n-tile (32), d-tile (64)
    const int tx = threadIdx.x, ty = threadIdx.y;   // 32 x 8
    const int n0 = tn * 32, d0 = td * 64;
    const float* src = (n0 < C_NUM) ? hi : hj;
    const int nc = (n0 < C_NUM) ? n0 : (n0 - C_NUM);
#pragma unroll
    for (int kk = 0; kk < 8; ++kk) {
        const int dl = kk * 8 + ty;
        tile[dl][tx] = src[(size_t)(d0 + dl) * C_NUM + nc + tx];
    }
    __syncthreads();
    // write phase: each thread emits one 16B chunk (8 halfs along d)
    const int tid = ty * 32 + tx;          // 0..255
    const int nl = tid >> 3, c = tid & 7;  // n-local 0..31, chunk 0..7
    const int n = n0 + nl;
    uint32_t h4[4];
#pragma unroll
    for (int q = 0; q < 4; ++q) {
        const float v0 = tile[c * 8 + 2 * q][nl] * H_SCALE;
        const float v1 = tile[c * 8 + 2 * q + 1][nl] * H_SCALE;
        const __half2 p = __floats2half2_rn(v0, v1);
        h4[q] = *(const uint32_t*)&p;
    }
    const int ks = d0 >> 6;
    const size_t off = (((size_t)(ks << 14) + (size_t)n) << 7)
                     + (uint32_t)((c ^ (n & 7)) << 4);
    *(uint4*)(g_Hs + off) = make_uint4(h4[0], h4[1], h4[2], h4[3]);
}

// ---------------- kernel 1: 128x256 tile f16 GEMM + two-sided LSE partials ----------------
__global__ void __launch_bounds__(256, 2) tile_kernel() {
    extern __shared__ char smem[];
    __shared__ float rowM[512], rowS[512], colM[512], colS[512];
    __shared__ __align__(8) uint64_t mbars[4];   // full0, full1, empty0, empty1
    const uint32_t sbase = smem_u32(smem);
    const uint32_t mfull = smem_u32(mbars), mempty = mfull + 16;
    const int tid = threadIdx.x;
    const int lane = tid & 31, wid = tid >> 5;
    const int warp_m = wid & 1, warp_n = wid >> 1;     // 2 x 4 warp grid, warp tile 64x64
    const int lrow = lane & 15, lhi = lane >> 4;
    const uint32_t kx = (uint32_t)(lrow & 7);
    const uint32_t aoffA = (uint32_t)(warp_m * 64 + lrow) * 128;
    const uint32_t aoffB = A_BYTES + (uint32_t)(warp_n * 64 + lrow) * 128;

    // decode tile index -> (I, J): tiles with I <= 2J+1, listed J-major
    int I, J;
    {
        int p = blockIdx.x; J = 0;
        while (p >= 2 * J + 2) { p -= 2 * J + 2; ++J; }
        I = p;
    }

    uint64_t gbase;
    asm("cvta.to.global.u64 %0, %1;" : "=l"(gbase) : "l"(g_Hs));

    if (tid == 0) {
        mbar_init(mfull, 1);    mbar_init(mfull + 8, 1);
        mbar_init(mempty, 8);   mbar_init(mempty + 8, 8);    // one arrive per warp
    }
    __syncthreads();
    if (tid == 0) {
        load_stage_bulk(sbase, gbase, I, J, 0, mfull);
        load_stage_bulk(sbase + STG_BYTES, gbase, I, J, 1, mfull + 8);
    }

    uint32_t acc[4][8][2];                 // f16x2 accumulators, 64 regs
#pragma unroll
    for (int mt = 0; mt < 4; ++mt)
#pragma unroll
        for (int nt = 0; nt < 8; ++nt) { acc[mt][nt][0] = 0u; acc[mt][nt][1] = 0u; }

    for (int ks = 0; ks < KSTAGES; ++ks) {
        const uint32_t b = (uint32_t)(ks & 1);
        // producer: issue stage ks+1 into the other buffer once all warps consumed ks-1
        if (tid == 0 && ks >= 1 && ks + 1 < KSTAGES) {
            const uint32_t nb = 1u - b;
            mbar_wait_relaxed(mempty + nb * 8, (uint32_t)(((ks - 1) >> 1) & 1));
            load_stage_bulk(sbase + nb * STG_BYTES, gbase, I, J, ks + 1, mfull + nb * 8);
        }
        // consumer: wait stage ks data
        mbar_wait(mfull + b * 8, (uint32_t)((ks >> 1) & 1));

        const uint32_t sb = sbase + b * STG_BYTES;
#pragma unroll
        for (int s = 0; s < 4; ++s) {                  // 4 x k16 within the 64-half stage
            const uint32_t co = (((uint32_t)(2 * s + lhi) ^ kx) << 4);
            uint32_t a[4][4], bb[4][4];
#pragma unroll
            for (int mt = 0; mt < 4; ++mt)
                ldsm4(sb + aoffA + mt * 2048 + co, a[mt][0], a[mt][1], a[mt][2], a[mt][3]);
#pragma unroll
            for (int p = 0; p < 4; ++p)
                ldsm4(sb + aoffB + p * 2048 + co, bb[p][0], bb[p][1], bb[p][2], bb[p][3]);
#pragma unroll
            for (int mt = 0; mt < 4; ++mt)
#pragma unroll
                for (int p = 0; p < 4; ++p) {
                    mma16816h(acc[mt][p * 2 + 0], a[mt], bb[p][0], bb[p][2]);
                    mma16816h(acc[mt][p * 2 + 1], a[mt], bb[p][1], bb[p][3]);
                }
        }
        if (lane == 0) mbar_arrive(mempty + b * 8);   // elected, non-blocking
    }

    // ---- diagonal masking (crossing tiles) and pos capture (partner tiles) ----
    // both live at cl == rl + 128*(I&1)
    const bool isCross = ((I >> 1) == J);
    const bool isPart  = (J == (I >> 1) + 32);
    if (isCross || isPart) {
        const int off = (I & 1) << 7;
#pragma unroll
        for (int mt = 0; mt < 4; ++mt)
#pragma unroll
            for (int nt = 0; nt < 8; ++nt)
#pragma unroll
                for (int h = 0; h < 2; ++h) {
                    const int rl = warp_m * 64 + mt * 16 + h * 8 + (lane >> 2);
                    const int cl0 = warp_n * 64 + nt * 8 + (lane & 3) * 2;
                    const int tgt = rl + off;
                    __half2 pv = *(__half2*)&acc[mt][nt][h];
                    if (isPart) {
                        const int r = I * 128 + rl;
                        if (cl0 == tgt) {
                            const float v = __low2float(pv);
                            g_pos[r] = v; g_pos[r + C_NUM] = v;
                        }
                        if (cl0 + 1 == tgt) {
                            const float v = __high2float(pv);
                            g_pos[r] = v; g_pos[r + C_NUM] = v;
                        }
                    } else {   // crossing: mask diagonal
                        if (cl0 == tgt)
                            pv = __halves2half2(__float2half(-60000.f), __high2half(pv));
                        if (cl0 + 1 == tgt)
                            pv = __halves2half2(__low2half(pv), __float2half(-60000.f));
                        *(__half2*)&acc[mt][nt][h] = pv;
                    }
                }
    }

    // ---- row-side: rows of block I over the 256 cols of block J ----
#pragma unroll
    for (int mt = 0; mt < 4; ++mt)
#pragma unroll
        for (int h = 0; h < 2; ++h) {
            float v[16];
#pragma unroll
            for (int nt = 0; nt < 8; ++nt) {
                const __half2 pv = *(const __half2*)&acc[mt][nt][h];
                v[2 * nt] = __low2float(pv); v[2 * nt + 1] = __high2float(pv);
            }
            float vm = v[0];
#pragma unroll
            for (int q = 1; q < 16; ++q) vm = fmaxf(vm, v[q]);
            vm = fmaxf(vm, __shfl_xor_sync(0xffffffffu, vm, 1));
            vm = fmaxf(vm, __shfl_xor_sync(0xffffffffu, vm, 2));
            float s = 0.f;
#pragma unroll
            for (int q = 0; q < 16; ++q) s += ex2f(v[q] - vm);
            s += __shfl_xor_sync(0xffffffffu, s, 1);
            s += __shfl_xor_sync(0xffffffffu, s, 2);
            if ((lane & 3) == 0) {
                const int rl = warp_m * 64 + mt * 16 + h * 8 + (lane >> 2);
                rowM[rl * 4 + warp_n] = vm;
                rowS[rl * 4 + warp_n] = s;
            }
        }

    // ---- col-side: the 256 cols of J as rows, over the 128 cols of I (non-crossing) ----
    if (!isCross) {
#pragma unroll
        for (int nt = 0; nt < 8; ++nt)
#pragma unroll
            for (int i = 0; i < 2; ++i) {
                float v[8];
#pragma unroll
                for (int mt = 0; mt < 4; ++mt)
#pragma unroll
                    for (int h = 0; h < 2; ++h) {
                        const __half2 pv = *(const __half2*)&acc[mt][nt][h];
                        v[mt * 2 + h] = i ? __high2float(pv) : __low2float(pv);
                    }
                float vm = v[0];
#pragma unroll
                for (int q = 1; q < 8; ++q) vm = fmaxf(vm, v[q]);
                vm = fmaxf(vm, __shfl_xor_sync(0xffffffffu, vm, 4));
                vm = fmaxf(vm, __shfl_xor_sync(0xffffffffu, vm, 8));
                vm = fmaxf(vm, __shfl_xor_sync(0xffffffffu, vm, 16));
                float s = 0.f;
#pragma unroll
                for (int q = 0; q < 8; ++q) s += ex2f(v[q] - vm);
                s += __shfl_xor_sync(0xffffffffu, s, 4);
                s += __shfl_xor_sync(0xffffffffu, s, 8);
                s += __shfl_xor_sync(0xffffffffu, s, 16);
                if (lane < 4) {
                    const int cl = warp_n * 64 + nt * 8 + lane * 2 + i;
                    colM[cl * 2 + warp_m] = vm;
                    colS[cl * 2 + warp_m] = s;
                }
            }
    }
    __syncthreads();

    if (tid < 128) {   // row-side store: slot J, rows I*128..+127
        float M = -1e30f;
#pragma unroll
        for (int g = 0; g < 4; ++g) M = fmaxf(M, rowM[tid * 4 + g]);
        float S = 0.f;
#pragma unroll
        for (int g = 0; g < 4; ++g) S += rowS[tid * 4 + g] * ex2f(rowM[tid * 4 + g] - M);
        g_pm[(size_t)J * N_TOT + I * 128 + tid] = M;
        g_ps[(size_t)J * N_TOT + I * 128 + tid] = S;
    }
    if (!isCross) {    // col-side store: slot 64+I, rows J*256..+255
        const float m0 = colM[tid * 2], m1 = colM[tid * 2 + 1];
        const float M = fmaxf(m0, m1);
        const float S = colS[tid * 2] * ex2f(m0 - M) + colS[tid * 2 + 1] * ex2f(m1 - M);
        g_pm[(size_t)(64 + I) * N_TOT + J * 256 + tid] = M;
        g_ps[(size_t)(64 + I) * N_TOT + J * 256 + tid] = S;
    }
}

// ---------------- kernel 2: merge valid slots per row (2-way ILP) ----------------
__global__ void merge_kernel() {
    __shared__ double red[128];
    const int r = blockIdx.x * 128 + threadIdx.x;
    const int I = r >> 7, Ih = I >> 1;
    float M0 = -1e30f, S0 = 0.f, M1 = -1e30f, S1 = 0.f;
    // row-side slots: J = Ih .. 63
    {
        int J = Ih;
        for (; J + 1 < NCOLB; J += 2) {
            const float ma = g_pm[(size_t)J * N_TOT + r];
            const float sa = g_ps[(size_t)J * N_TOT + r];
            const float mb = g_pm[(size_t)(J + 1) * N_TOT + r];
            const float sb = g_ps[(size_t)(J + 1) * N_TOT + r];
            float Mn = fmaxf(M0, ma);
            S0 = S0 * ex2f(M0 - Mn) + sa * ex2f(ma - Mn); M0 = Mn;
            Mn = fmaxf(M1, mb);
            S1 = S1 * ex2f(M1 - Mn) + sb * ex2f(mb - Mn); M1 = Mn;
        }
        for (; J < NCOLB; ++J) {
            const float m  = g_pm[(size_t)J * N_TOT + r];
            const float sv = g_ps[(size_t)J * N_TOT + r];
            const float Mn = fmaxf(M0, m);
            S0 = S0 * ex2f(M0 - Mn) + sv * ex2f(m - Mn); M0 = Mn;
        }
    }
    // col-side slots: I2 = 0 .. 2*Ih-1
    {
        int I2 = 0;
        for (; I2 + 1 < 2 * Ih; I2 += 2) {
            const float ma = g_pm[(size_t)(64 + I2) * N_TOT + r];
            const float sa = g_ps[(size_t)(64 + I2) * N_TOT + r];
            const float mb = g_pm[(size_t)(65 + I2) * N_TOT + r];
            const float sb = g_ps[(size_t)(65 + I2) * N_TOT + r];
            float Mn = fmaxf(M0, ma);
            S0 = S0 * ex2f(M0 - Mn) + sa * ex2f(ma - Mn); M0 = Mn;
            Mn = fmaxf(M1, mb);
            S1 = S1 * ex2f(M1 - Mn) + sb * ex2f(mb - Mn); M1 = Mn;
        }
        for (; I2 < 2 * Ih; ++I2) {
            const float m  = g_pm[(size_t)(64 + I2) * N_TOT + r];
            const float sv = g_ps[(size_t)(64 + I2) * N_TOT + r];
            const float Mn = fmaxf(M0, m);
            S0 = S0 * ex2f(M0 - Mn) + sv * ex2f(m - Mn); M0 = Mn;
        }
    }
    const float M = fmaxf(M0, M1);
    const float S = S0 * ex2f(M0 - M) + S1 * ex2f(M1 - M);
    red[threadIdx.x] = ((double)M + (double)lg2f(S) - (double)g_pos[r]) * LN2_D;
    __syncthreads();
    if (threadIdx.x == 0) {
        double s = 0.0;
        for (int i = 0; i < 128; ++i) s += red[i];
        g_partial[blockIdx.x] = s;
    }
}

// ---------------- kernel 3: final scalar (parallel reduce) ----------------
__global__ void finalize_kernel(float* out) {
    __shared__ double red[128];
    red[threadIdx.x] = g_partial[threadIdx.x];
    __syncthreads();
#pragma unroll
    for (int off = 64; off > 0; off >>= 1) {
        if (threadIdx.x < off) red[threadIdx.x] += red[threadIdx.x + off];
        __syncthreads();
    }
    if (threadIdx.x == 0) out[0] = (float)(red[0] / (double)N_TOT);
}

// ---------------- launch ----------------
extern "C" void kernel_launch(void* const* d_in, const int* in_sizes, int n_in,
                              void* d_out, int out_size) {
    const float* hi = (const float*)d_in[0];
    const float* hj = (const float*)d_in[1];
    float* out = (float*)d_out;

    dim3 cg(N_TOT / 32, D_DIM / 64), cb(32, 8);
    convert_kernel<<<cg, cb>>>(hi, hj);

    cudaFuncSetAttribute(tile_kernel, cudaFuncAttributeMaxDynamicSharedMemorySize, SMEM_TOTAL);
    tile_kernel<<<NTILES, 256, SMEM_TOTAL>>>();

    merge_kernel<<<NBLK, 128>>>();
    finalize_kernel<<<1, 128>>>(out);
}